// round 1
// baseline (speedup 1.0000x reference)
#include <cuda_runtime.h>
#include <math.h>

#define TT   512      // Ttot = T*Ts
#define BB   128      // batch
#define HH   512      // hidden
#define CC   32       // input channels
#define TIN  128      // input time steps
#define NCHN 2048     // H*Ts conv output channels
#define HORZ 96
#define NELEM (TT*BB*HH)   // 33,554,432

// ---------------- scratch (device globals; no allocs allowed) ----------------
__device__ float g_conv[BB*NCHN*TIN];   // (B, 2048, T)
__device__ float g_bufA[NELEM];         // (Ttot, B, H)
__device__ float g_bufB[NELEM];
__device__ float g_Q[NELEM];
__device__ float g_K[NELEM];
__device__ float g_V[NELEM];
__device__ float g_wpart[4*BB*TT];
__device__ float g_wsum[BB*TT];
__device__ float g_feat[BB*HH];
__device__ float g_featn[BB*HH];
__device__ float g_chm[NCHN];
__device__ float g_chr[NCHN];

// ---------------- conv1d (C->NCHN, k=3, pad=1), 8 channels per block --------
__global__ void conv_kernel(const float* __restrict__ x,
                            const float* __restrict__ w,
                            const float* __restrict__ cb) {
    __shared__ float xs[130][33];     // time rows -1..128, padded cols
    __shared__ float ws[8*96];
    int b  = blockIdx.y;
    int c0 = blockIdx.x * 8;
    int t  = threadIdx.x;             // 128 threads = output time
    for (int i = t; i < 130*32; i += 128) {
        int r = i >> 5, ci = i & 31;
        int tt = r - 1;
        xs[r][ci] = (tt >= 0 && tt < TIN) ? x[(b*TIN + tt)*CC + ci] : 0.0f;
    }
    for (int i = t; i < 8*96; i += 128) ws[i] = w[c0*96 + i];
    __syncthreads();

    float acc[8];
    #pragma unroll
    for (int cc = 0; cc < 8; cc++) acc[cc] = cb[c0+cc];
    #pragma unroll
    for (int i = 0; i < 32; i++) {
        float x0 = xs[t][i], x1 = xs[t+1][i], x2 = xs[t+2][i];
        #pragma unroll
        for (int cc = 0; cc < 8; cc++) {
            acc[cc] += ws[cc*96 + i*3+0]*x0
                     + ws[cc*96 + i*3+1]*x1
                     + ws[cc*96 + i*3+2]*x2;
        }
    }
    #pragma unroll
    for (int cc = 0; cc < 8; cc++)
        g_conv[(b*NCHN + c0+cc)*TIN + t] = acc[cc];
}

// ---------------- per-channel BN1 stats over (B,T) ---------------------------
__global__ void chan_stats_kernel() {
    int c = blockIdx.x;
    int tid = threadIdx.x;  // 256
    float s = 0.f, sq = 0.f;
    for (int i = tid; i < BB*TIN; i += 256) {
        int b = i >> 7, t = i & 127;
        float v = g_conv[(b*NCHN + c)*TIN + t];
        s += v; sq += v*v;
    }
    __shared__ float ss[256], sqs[256];
    ss[tid] = s; sqs[tid] = sq;
    __syncthreads();
    for (int o = 128; o > 0; o >>= 1) {
        if (tid < o) { ss[tid] += ss[tid+o]; sqs[tid] += sqs[tid+o]; }
        __syncthreads();
    }
    if (tid == 0) {
        float m   = ss[0] * (1.0f/(BB*TIN));
        float var = sqs[0] * (1.0f/(BB*TIN)) - m*m;
        g_chm[c] = m;
        g_chr[c] = rsqrtf(var + 1e-5f);
    }
}

// ---------------- BN1 apply + relayout (B,2048,T) -> (Ttot,B,H) -------------
__global__ void bn1_apply_kernel(const float* __restrict__ g,
                                 const float* __restrict__ bb) {
    int idx = blockIdx.x*256 + threadIdx.x;   // output index in (tau,b,hh)
    int hh  = idx & 511;
    int b   = (idx >> 9) & 127;
    int tau = idx >> 16;
    int t   = tau >> 2, ts = tau & 3;
    int c   = ts*HH + hh;
    float v = g_conv[(b*NCHN + c)*TIN + t];
    g_bufA[idx] = (v - g_chm[c]) * g_chr[c] * g[c] + bb[c];
}

// ---------------- LIF scan: g_bufA -> g_bufB ---------------------------------
__global__ void lif_scan_kernel(const float* __restrict__ beta_arr, int store_mem) {
    int idx = blockIdx.x*blockDim.x + threadIdx.x;  // 0..65535  (b*H + h)
    float beta = fminf(fmaxf(beta_arr[idx & 511], 0.0f), 0.99f);
    float mem = 0.0f;
    #pragma unroll 4
    for (int t = 0; t < TT; t++) {
        float cur   = g_bufA[t*(BB*HH) + idx];
        float reset = (mem > 1.0f) ? 1.0f : 0.0f;
        mem = beta*mem + cur - reset;
        float sp = (mem > 1.0f) ? 1.0f : 0.0f;
        g_bufB[t*(BB*HH) + idx] = store_mem ? mem : sp;
    }
}

// ---------------- per-step BN over batch: g_bufB -> g_bufA -------------------
__global__ void bn_step_kernel(const float* __restrict__ g,
                               const float* __restrict__ bb) {
    int t = blockIdx.x;
    int h = blockIdx.y*128 + threadIdx.x;
    int base = t*(BB*HH) + h;
    float s = 0.f, sq = 0.f;
    #pragma unroll 4
    for (int b = 0; b < BB; b++) {
        float v = g_bufB[base + b*HH];
        s += v; sq += v*v;
    }
    float m    = s * (1.0f/BB);
    float rstd = rsqrtf(sq*(1.0f/BB) - m*m + 1e-5f);
    float gg = g[h]*rstd;
    float bo = bb[h] - m*gg;
    #pragma unroll 4
    for (int b = 0; b < BB; b++)
        g_bufA[base + b*HH] = g_bufB[base + b*HH]*gg + bo;
}

// ---------------- GEMM: C(sel) = mem3(65536x512) @ W^T + bias ---------------
__global__ __launch_bounds__(256) void gemm_xwT_kernel(int sel,
        const float* __restrict__ W, const float* __restrict__ bias) {
    const float* __restrict__ A = g_bufB;  // mem3, row m = t*B + b
    float* __restrict__ C = (sel == 0) ? g_Q : (sel == 1) ? g_K : g_V;

    __shared__ __align__(16) float As[16][128];
    __shared__ __align__(16) float Bs[16][128];
    int tid = threadIdx.x;
    int n0 = blockIdx.x * 128;
    int m0 = blockIdx.y * 128;
    int tx = tid & 15, ty = tid >> 4;
    float acc[8][8] = {};

    for (int k0 = 0; k0 < HH; k0 += 16) {
        #pragma unroll
        for (int it = 0; it < 2; it++) {
            int flat = tid + it*256;
            int r = flat >> 2, c = flat & 3;
            float4 va = *(const float4*)(A + (m0 + r)*HH + k0 + c*4);
            As[c*4+0][r] = va.x; As[c*4+1][r] = va.y;
            As[c*4+2][r] = va.z; As[c*4+3][r] = va.w;
            float4 vb = *(const float4*)(W + (n0 + r)*HH + k0 + c*4);
            Bs[c*4+0][r] = vb.x; Bs[c*4+1][r] = vb.y;
            Bs[c*4+2][r] = vb.z; Bs[c*4+3][r] = vb.w;
        }
        __syncthreads();
        #pragma unroll
        for (int k = 0; k < 16; k++) {
            float a[8], b[8];
            *(float4*)(a)   = *(const float4*)&As[k][ty*8];
            *(float4*)(a+4) = *(const float4*)&As[k][ty*8+4];
            *(float4*)(b)   = *(const float4*)&Bs[k][tx*8];
            *(float4*)(b+4) = *(const float4*)&Bs[k][tx*8+4];
            #pragma unroll
            for (int i = 0; i < 8; i++)
                #pragma unroll
                for (int j = 0; j < 8; j++)
                    acc[i][j] += a[i]*b[j];
        }
        __syncthreads();
    }
    #pragma unroll
    for (int i = 0; i < 8; i++) {
        int m = m0 + ty*8 + i;
        #pragma unroll
        for (int j = 0; j < 8; j++)
            C[m*HH + n0 + tx*8 + j] = acc[i][j] + bias[n0 + tx*8 + j];
    }
}

// ---------------- per-batch QK^T + sigmoid + column mean partials -----------
__global__ __launch_bounds__(256) void qk_attn_kernel() {
    __shared__ __align__(16) float As[16][128];
    __shared__ __align__(16) float Bs[16][128];
    __shared__ float red[16][128];
    int b  = blockIdx.z;
    int n0 = blockIdx.x * 128;   // s tile
    int m0 = blockIdx.y * 128;   // t tile
    int tid = threadIdx.x;
    int tx = tid & 15, ty = tid >> 4;
    float acc[8][8] = {};

    for (int k0 = 0; k0 < HH; k0 += 16) {
        #pragma unroll
        for (int it = 0; it < 2; it++) {
            int flat = tid + it*256;
            int r = flat >> 2, c = flat & 3;
            float4 va = *(const float4*)(g_Q + ((m0 + r)*BB + b)*HH + k0 + c*4);
            As[c*4+0][r] = va.x; As[c*4+1][r] = va.y;
            As[c*4+2][r] = va.z; As[c*4+3][r] = va.w;
            float4 vb = *(const float4*)(g_K + ((n0 + r)*BB + b)*HH + k0 + c*4);
            Bs[c*4+0][r] = vb.x; Bs[c*4+1][r] = vb.y;
            Bs[c*4+2][r] = vb.z; Bs[c*4+3][r] = vb.w;
        }
        __syncthreads();
        #pragma unroll
        for (int k = 0; k < 16; k++) {
            float a[8], bb2[8];
            *(float4*)(a)    = *(const float4*)&As[k][ty*8];
            *(float4*)(a+4)  = *(const float4*)&As[k][ty*8+4];
            *(float4*)(bb2)  = *(const float4*)&Bs[k][tx*8];
            *(float4*)(bb2+4)= *(const float4*)&Bs[k][tx*8+4];
            #pragma unroll
            for (int i = 0; i < 8; i++)
                #pragma unroll
                for (int j = 0; j < 8; j++)
                    acc[i][j] += a[i]*bb2[j];
        }
        __syncthreads();
    }
    const float scale = 0.04419417382415922f;  // 512^-0.5
    #pragma unroll
    for (int j = 0; j < 8; j++) {
        float s = 0.f;
        #pragma unroll
        for (int i = 0; i < 8; i++)
            s += 1.0f / (1.0f + __expf(-acc[i][j]*scale));
        red[ty][tx*8 + j] = s;
    }
    __syncthreads();
    if (tid < 128) {
        float v = 0.f;
        #pragma unroll
        for (int yy = 0; yy < 16; yy++) v += red[yy][tid];
        g_wpart[blockIdx.y*(BB*TT) + b*TT + n0 + tid] = v;  // deterministic
    }
}

__global__ void reduce_w_kernel() {
    int i = blockIdx.x*256 + threadIdx.x;   // BB*TT = 65536
    g_wsum[i] = g_wpart[i] + g_wpart[BB*TT + i]
              + g_wpart[2*BB*TT + i] + g_wpart[3*BB*TT + i];
}

// ---------------- feat[b,d] = (1/Ttot) * sum_s wsum[b,s]*V[b,s,d] ------------
__global__ void feat_v_kernel() {
    int b = blockIdx.y;
    int d = blockIdx.x*128 + threadIdx.x;
    float acc = 0.f;
    #pragma unroll 4
    for (int s = 0; s < TT; s++)
        acc += g_wsum[b*TT + s] * g_V[(s*BB + b)*HH + d];
    g_feat[b*HH + d] = acc * (1.0f/TT);
}

// ---------------- BN over batch on feat --------------------------------------
__global__ void feat_bn_kernel(const float* __restrict__ g,
                               const float* __restrict__ bb) {
    int d = threadIdx.x;  // 512
    float s = 0.f, sq = 0.f;
    for (int b = 0; b < BB; b++) {
        float v = g_feat[b*HH + d];
        s += v; sq += v*v;
    }
    float m = s * (1.0f/BB);
    float rstd = rsqrtf(sq*(1.0f/BB) - m*m + 1e-5f);
    float gg = g[d]*rstd;
    float bo = bb[d] - m*gg;
    for (int b = 0; b < BB; b++)
        g_featn[b*HH + d] = g_feat[b*HH + d]*gg + bo;
}

// ---------------- final linear H -> 96 ---------------------------------------
__global__ void final_lin_kernel(const float* __restrict__ wh,
                                 const float* __restrict__ bh,
                                 float* __restrict__ out) {
    __shared__ float fs[HH];
    int b = blockIdx.x;
    int o = threadIdx.x;  // 96
    for (int i = o; i < HH; i += 96) fs[i] = g_featn[b*HH + i];
    __syncthreads();
    float acc = bh[o];
    for (int d = 0; d < HH; d++) acc += fs[d] * wh[o*HH + d];
    out[b*HORZ + o] = acc;
}

// ---------------- launch ------------------------------------------------------
extern "C" void kernel_launch(void* const* d_in, const int* in_sizes, int n_in,
                              void* d_out, int out_size) {
    const float* x        = (const float*)d_in[0];
    const float* conv_w   = (const float*)d_in[1];
    const float* conv_b   = (const float*)d_in[2];
    const float* bn1_g    = (const float*)d_in[3];
    const float* bn1_b    = (const float*)d_in[4];
    const float* beta_enc = (const float*)d_in[5];
    const float* bn2_g    = (const float*)d_in[6];
    const float* bn2_b    = (const float*)d_in[7];
    const float* beta2    = (const float*)d_in[8];
    const float* bn3_g    = (const float*)d_in[9];
    const float* bn3_b    = (const float*)d_in[10];
    const float* beta3    = (const float*)d_in[11];
    const float* wq       = (const float*)d_in[12];
    const float* bq       = (const float*)d_in[13];
    const float* wk       = (const float*)d_in[14];
    const float* bk       = (const float*)d_in[15];
    const float* wv       = (const float*)d_in[16];
    const float* bv       = (const float*)d_in[17];
    const float* bna_g    = (const float*)d_in[18];
    const float* bna_b    = (const float*)d_in[19];
    const float* wh       = (const float*)d_in[20];
    const float* bh       = (const float*)d_in[21];
    float* out = (float*)d_out;

    conv_kernel<<<dim3(NCHN/8, BB), 128>>>(x, conv_w, conv_b);
    chan_stats_kernel<<<NCHN, 256>>>();
    bn1_apply_kernel<<<NELEM/256, 256>>>(bn1_g, bn1_b);

    lif_scan_kernel<<<512, 128>>>(beta_enc, 0);   // A -> B (spikes)
    bn_step_kernel<<<dim3(TT, 4), 128>>>(bn2_g, bn2_b);  // B -> A
    lif_scan_kernel<<<512, 128>>>(beta2, 0);      // A -> B
    bn_step_kernel<<<dim3(TT, 4), 128>>>(bn3_g, bn3_b);  // B -> A
    lif_scan_kernel<<<512, 128>>>(beta3, 1);      // A -> B (mem3)

    gemm_xwT_kernel<<<dim3(HH/128, (TT*BB)/128), 256>>>(0, wq, bq);
    gemm_xwT_kernel<<<dim3(HH/128, (TT*BB)/128), 256>>>(1, wk, bk);
    gemm_xwT_kernel<<<dim3(HH/128, (TT*BB)/128), 256>>>(2, wv, bv);

    qk_attn_kernel<<<dim3(TT/128, TT/128, BB), 256>>>();
    reduce_w_kernel<<<(BB*TT)/256, 256>>>();
    feat_v_kernel<<<dim3(HH/128, BB), 128>>>();
    feat_bn_kernel<<<1, HH>>>(bna_g, bna_b);
    final_lin_kernel<<<BB, HORZ>>>(wh, bh, out);
}